// round 1
// baseline (speedup 1.0000x reference)
#include <cuda_runtime.h>
#include <cuda_bf16.h>
#include <cstdint>

#define IN_F   4096
#define OUT_F  4096
#define M_TOK  8192
#define NKTOT  (IN_F / 32)

// Scratch (allocation-free rule: __device__ globals). 192 MB total, zero-init .bss.
__device__ __align__(256) __nv_bfloat16 g_w_hi[(size_t)OUT_F * IN_F];
__device__ __align__(256) __nv_bfloat16 g_w_lo[(size_t)OUT_F * IN_F];
__device__ __align__(256) __nv_bfloat16 g_x_hi[(size_t)M_TOK * IN_F];
__device__ __align__(256) __nv_bfloat16 g_x_lo[(size_t)M_TOK * IN_F];

// ---------------------------------------------------------------------------
// Kernel 1: weight reconstruction + bf16 hi/lo split.
// w_recon[o=p*1024 + n/16][i=(n%16)*256 + c]
//   = (sum_l vq[n,p,l]*w_dec[p,l,c] + b_dec[p,c]) * (d_std[p]+eps) + d_mean[p]
// ---------------------------------------------------------------------------
__global__ void recon_kernel(const float* __restrict__ vq,
                             const float* __restrict__ w_dec,
                             const float* __restrict__ b_dec,
                             const float* __restrict__ d_mean,
                             const float* __restrict__ d_std) {
    __shared__ float s_wdec[32][256];   // 32 KB
    __shared__ float s_b[256];
    __shared__ float s_v[64][32];       // 8 KB

    const int p   = blockIdx.y;
    const int tid = threadIdx.x;
    const int n0  = blockIdx.x * 64;

    const float* wd = w_dec + p * 32 * 256;
    for (int i = tid; i < 32 * 256; i += 256)
        s_wdec[i >> 8][i & 255] = wd[i];
    s_b[tid] = b_dec[p * 256 + tid];
    for (int i = tid; i < 64 * 32; i += 256) {
        int j = i >> 5, l = i & 31;
        s_v[j][l] = vq[(n0 + j) * 128 + p * 32 + l];
    }
    __syncthreads();

    const float scale = d_std[p] + 1e-6f;
    const float mean  = d_mean[p];
    const int   c     = tid;

    for (int j = 0; j < 64; ++j) {
        float acc = s_b[c];
#pragma unroll
        for (int l = 0; l < 32; ++l)
            acc = fmaf(s_v[j][l], s_wdec[l][c], acc);
        float w = fmaf(acc, scale, mean);
        __nv_bfloat16 hi = __float2bfloat16_rn(w);
        float lo = w - __bfloat162float(hi);
        int n   = n0 + j;
        int o   = p * 1024 + (n >> 4);
        int col = ((n & 15) << 8) + c;
        size_t idx = (size_t)o * IN_F + col;
        g_w_hi[idx] = hi;
        g_w_lo[idx] = __float2bfloat16_rn(lo);
    }
}

// ---------------------------------------------------------------------------
// Kernel 2: split x (fp32) -> x_hi, x_lo (bf16)
// ---------------------------------------------------------------------------
__global__ void split_x_kernel(const float4* __restrict__ x4) {
    int i = blockIdx.x * blockDim.x + threadIdx.x;   // 0 .. M_TOK*IN_F/4 - 1
    float4 v = x4[i];
    __nv_bfloat16 h0 = __float2bfloat16_rn(v.x);
    __nv_bfloat16 h1 = __float2bfloat16_rn(v.y);
    __nv_bfloat16 h2 = __float2bfloat16_rn(v.z);
    __nv_bfloat16 h3 = __float2bfloat16_rn(v.w);
    __nv_bfloat16 l0 = __float2bfloat16_rn(v.x - __bfloat162float(h0));
    __nv_bfloat16 l1 = __float2bfloat16_rn(v.y - __bfloat162float(h1));
    __nv_bfloat16 l2 = __float2bfloat16_rn(v.z - __bfloat162float(h2));
    __nv_bfloat16 l3 = __float2bfloat16_rn(v.w - __bfloat162float(h3));
    __nv_bfloat162* H = reinterpret_cast<__nv_bfloat162*>(g_x_hi);
    __nv_bfloat162* L = reinterpret_cast<__nv_bfloat162*>(g_x_lo);
    H[2 * i]     = __halves2bfloat162(h0, h1);
    H[2 * i + 1] = __halves2bfloat162(h2, h3);
    L[2 * i]     = __halves2bfloat162(l0, l1);
    L[2 * i + 1] = __halves2bfloat162(l2, l3);
}

// ---------------------------------------------------------------------------
// Kernel 3: GEMM out[t][o] = sum_i x[t][i]*w[o][i] + bias[o]
// bf16x3 split: Ahi*Bhi + Ahi*Blo + Alo*Bhi, fp32 accumulation.
// Block tile 128x128, K-tile 32, 256 threads (8 warps of 64x32),
// cp.async double buffering, ldmatrix + mma.sync.m16n8k16.
// ---------------------------------------------------------------------------
#define SM_STRIDE 40                 // 32 + 8 pad (elements) -> conflict-free ldmatrix
#define ARR_ELEMS (128 * SM_STRIDE)  // 5120
#define STAGE_ELEMS (4 * ARR_ELEMS)  // 20480
#define STAGE_BYTES (STAGE_ELEMS * 2)
#define OFF_AHI 0
#define OFF_ALO ARR_ELEMS
#define OFF_BHI (2 * ARR_ELEMS)
#define OFF_BLO (3 * ARR_ELEMS)

__device__ __forceinline__ void mma_bf16(float* c, const uint32_t* a, const uint32_t* b) {
    asm volatile(
        "mma.sync.aligned.m16n8k16.row.col.f32.bf16.bf16.f32 "
        "{%0,%1,%2,%3}, {%4,%5,%6,%7}, {%8,%9}, {%0,%1,%2,%3};\n"
        : "+f"(c[0]), "+f"(c[1]), "+f"(c[2]), "+f"(c[3])
        : "r"(a[0]), "r"(a[1]), "r"(a[2]), "r"(a[3]), "r"(b[0]), "r"(b[1]));
}

__device__ __forceinline__ void ldsm_x4(uint32_t* r, uint32_t addr) {
    asm volatile("ldmatrix.sync.aligned.m8n8.x4.shared.b16 {%0,%1,%2,%3}, [%4];\n"
                 : "=r"(r[0]), "=r"(r[1]), "=r"(r[2]), "=r"(r[3]) : "r"(addr));
}

__device__ __forceinline__ void cp16(uint32_t saddr, const void* g) {
    asm volatile("cp.async.cg.shared.global [%0], [%1], 16;\n"
                 :: "r"(saddr), "l"(g) : "memory");
}

__device__ __forceinline__ void load_tile(uint32_t st, int k0,
                                          const __nv_bfloat16* gxh, const __nv_bfloat16* gxl,
                                          const __nv_bfloat16* gwh, const __nv_bfloat16* gwl,
                                          int r0, int c0, int r1, int c1) {
    cp16(st + (uint32_t)(OFF_AHI + r0 * SM_STRIDE + c0) * 2, gxh + (size_t)r0 * IN_F + k0 + c0);
    cp16(st + (uint32_t)(OFF_AHI + r1 * SM_STRIDE + c1) * 2, gxh + (size_t)r1 * IN_F + k0 + c1);
    cp16(st + (uint32_t)(OFF_ALO + r0 * SM_STRIDE + c0) * 2, gxl + (size_t)r0 * IN_F + k0 + c0);
    cp16(st + (uint32_t)(OFF_ALO + r1 * SM_STRIDE + c1) * 2, gxl + (size_t)r1 * IN_F + k0 + c1);
    cp16(st + (uint32_t)(OFF_BHI + r0 * SM_STRIDE + c0) * 2, gwh + (size_t)r0 * IN_F + k0 + c0);
    cp16(st + (uint32_t)(OFF_BHI + r1 * SM_STRIDE + c1) * 2, gwh + (size_t)r1 * IN_F + k0 + c1);
    cp16(st + (uint32_t)(OFF_BLO + r0 * SM_STRIDE + c0) * 2, gwl + (size_t)r0 * IN_F + k0 + c0);
    cp16(st + (uint32_t)(OFF_BLO + r1 * SM_STRIDE + c1) * 2, gwl + (size_t)r1 * IN_F + k0 + c1);
    asm volatile("cp.async.commit_group;\n" ::: "memory");
}

__global__ __launch_bounds__(256)
void gemm_kernel(const float* __restrict__ bias, float* __restrict__ out) {
    extern __shared__ __nv_bfloat16 sm[];
    const uint32_t sbase = (uint32_t)__cvta_generic_to_shared(sm);

    const int tid  = threadIdx.x;
    const int lane = tid & 31;
    const int warp = tid >> 5;
    const int wm   = warp >> 2;   // 0..1
    const int wn   = warp & 3;    // 0..3
    const int bm   = blockIdx.y;  // 0..63
    const int bn   = blockIdx.x;  // 0..31

    const __nv_bfloat16* gxh = g_x_hi + (size_t)bm * 128 * IN_F;
    const __nv_bfloat16* gxl = g_x_lo + (size_t)bm * 128 * IN_F;
    const __nv_bfloat16* gwh = g_w_hi + (size_t)bn * 128 * IN_F;
    const __nv_bfloat16* gwl = g_w_lo + (size_t)bn * 128 * IN_F;

    // gmem->smem mapping: 512 chunks of 16B per array, 2 per thread
    const int q0 = tid, q1 = tid + 256;
    const int r0 = q0 >> 2, c0 = (q0 & 3) << 3;
    const int r1 = q1 >> 2, c1 = (q1 & 3) << 3;

    float acc[4][4][4] = {};

    load_tile(sbase, 0, gxh, gxl, gwh, gwl, r0, c0, r1, c1);

    for (int kt = 0; kt < NKTOT; ++kt) {
        if (kt + 1 < NKTOT) {
            load_tile(sbase + ((kt + 1) & 1) * STAGE_BYTES, (kt + 1) * 32,
                      gxh, gxl, gwh, gwl, r0, c0, r1, c1);
            asm volatile("cp.async.wait_group 1;\n" ::: "memory");
        } else {
            asm volatile("cp.async.wait_group 0;\n" ::: "memory");
        }
        __syncthreads();

        const uint32_t st = sbase + (kt & 1) * STAGE_BYTES;

#pragma unroll
        for (int ks = 0; ks < 2; ++ks) {
            uint32_t ahi[4][4], alo[4][4], bhi[4][2], blo[4][2];

            const int arow = wm * 64 + (lane & 15);
            const int acol = ks * 16 + ((lane >> 4) << 3);
#pragma unroll
            for (int mt = 0; mt < 4; ++mt) {
                uint32_t off = (uint32_t)((arow + mt * 16) * SM_STRIDE + acol);
                ldsm_x4(ahi[mt], st + (OFF_AHI + off) * 2);
                ldsm_x4(alo[mt], st + (OFF_ALO + off) * 2);
            }

            const int nrow = wn * 32 + (lane & 7) + ((lane >> 4) << 3);
            const int kcol = ks * 16 + (lane & 8);
#pragma unroll
            for (int ntp = 0; ntp < 2; ++ntp) {
                uint32_t off = (uint32_t)((nrow + ntp * 16) * SM_STRIDE + kcol);
                uint32_t rr[4];
                ldsm_x4(rr, st + (OFF_BHI + off) * 2);
                bhi[2 * ntp][0] = rr[0]; bhi[2 * ntp][1] = rr[1];
                bhi[2 * ntp + 1][0] = rr[2]; bhi[2 * ntp + 1][1] = rr[3];
                ldsm_x4(rr, st + (OFF_BLO + off) * 2);
                blo[2 * ntp][0] = rr[0]; blo[2 * ntp][1] = rr[1];
                blo[2 * ntp + 1][0] = rr[2]; blo[2 * ntp + 1][1] = rr[3];
            }

#pragma unroll
            for (int mt = 0; mt < 4; ++mt)
#pragma unroll
                for (int nt = 0; nt < 4; ++nt)
                    mma_bf16(acc[mt][nt], ahi[mt], bhi[nt]);
#pragma unroll
            for (int mt = 0; mt < 4; ++mt)
#pragma unroll
                for (int nt = 0; nt < 4; ++nt)
                    mma_bf16(acc[mt][nt], ahi[mt], blo[nt]);
#pragma unroll
            for (int mt = 0; mt < 4; ++mt)
#pragma unroll
                for (int nt = 0; nt < 4; ++nt)
                    mma_bf16(acc[mt][nt], alo[mt], bhi[nt]);
        }
        __syncthreads();
    }

    // Epilogue: add bias, write fp32
#pragma unroll
    for (int mt = 0; mt < 4; ++mt) {
        int t = bm * 128 + wm * 64 + mt * 16 + (lane >> 2);
#pragma unroll
        for (int nt = 0; nt < 4; ++nt) {
            int o = bn * 128 + wn * 32 + nt * 8 + ((lane & 3) << 1);
            float b0 = bias[o], b1 = bias[o + 1];
            float2* p0 = reinterpret_cast<float2*>(out + (size_t)t * OUT_F + o);
            float2* p1 = reinterpret_cast<float2*>(out + (size_t)(t + 8) * OUT_F + o);
            *p0 = make_float2(acc[mt][nt][0] + b0, acc[mt][nt][1] + b1);
            *p1 = make_float2(acc[mt][nt][2] + b0, acc[mt][nt][3] + b1);
        }
    }
}

// ---------------------------------------------------------------------------
extern "C" void kernel_launch(void* const* d_in, const int* in_sizes, int n_in,
                              void* d_out, int out_size) {
    (void)in_sizes; (void)n_in; (void)out_size;
    const float* x      = (const float*)d_in[0];
    const float* vq     = (const float*)d_in[1];
    const float* w_dec  = (const float*)d_in[2];
    const float* b_dec  = (const float*)d_in[3];
    const float* d_mean = (const float*)d_in[4];
    const float* d_std  = (const float*)d_in[5];
    const float* bias   = (const float*)d_in[6];
    float* out = (float*)d_out;

    recon_kernel<<<dim3(256, 4), 256>>>(vq, w_dec, b_dec, d_mean, d_std);
    split_x_kernel<<<(M_TOK * IN_F / 4) / 256, 256>>>((const float4*)x);

    cudaFuncSetAttribute(gemm_kernel, cudaFuncAttributeMaxDynamicSharedMemorySize,
                         2 * STAGE_BYTES);
    gemm_kernel<<<dim3(32, 64), 256, 2 * STAGE_BYTES>>>(bias, out);
}

// round 4
// speedup vs baseline: 4.2691x; 4.2691x over previous
#include <cuda_runtime.h>
#include <cuda_bf16.h>
#include <cstdint>

#define IN_F   4096
#define OUT_F  4096
#define M_TOK  8192
#define XK     256                      // stage-1 contraction (x_flat cols)
#define K2     512                      // stage-2 contraction = 16*32
#define YPITCH ((size_t)M_TOK * K2)     // per-p Y matrix elems
#define VPITCH ((size_t)1024 * K2)      // per-p V matrix elems

// Scratch (allocation-free rule: __device__ globals).
__device__ __align__(256) __nv_bfloat16 g_wd_hi[128 * 256];
__device__ __align__(256) __nv_bfloat16 g_wd_lo[128 * 256];
__device__ __align__(256) __nv_bfloat16 g_y_hi[4 * YPITCH];
__device__ __align__(256) __nv_bfloat16 g_y_lo[4 * YPITCH];
__device__ __align__(256) __nv_bfloat16 g_v_hi[4 * VPITCH];
__device__ __align__(256) __nv_bfloat16 g_v_lo[4 * VPITCH];
__device__ float g_xs[M_TOK];
__device__ float g_xb[M_TOK * 4];

// ---------------------------------------------------------------------------
// small helpers
// ---------------------------------------------------------------------------
__device__ __forceinline__ void bf_split(float v, __nv_bfloat16& hi, __nv_bfloat16& lo) {
    hi = __float2bfloat16_rn(v);
    lo = __float2bfloat16_rn(v - __bfloat162float(hi));
}
__device__ __forceinline__ void mma_bf16(float* c, const uint32_t* a, const uint32_t* b) {
    asm volatile(
        "mma.sync.aligned.m16n8k16.row.col.f32.bf16.bf16.f32 "
        "{%0,%1,%2,%3}, {%4,%5,%6,%7}, {%8,%9}, {%0,%1,%2,%3};\n"
        : "+f"(c[0]), "+f"(c[1]), "+f"(c[2]), "+f"(c[3])
        : "r"(a[0]), "r"(a[1]), "r"(a[2]), "r"(a[3]), "r"(b[0]), "r"(b[1]));
}
__device__ __forceinline__ void ldsm_x4(uint32_t* r, uint32_t addr) {
    asm volatile("ldmatrix.sync.aligned.m8n8.x4.shared.b16 {%0,%1,%2,%3}, [%4];\n"
                 : "=r"(r[0]), "=r"(r[1]), "=r"(r[2]), "=r"(r[3]) : "r"(addr));
}
__device__ __forceinline__ void cp16(uint32_t saddr, const void* g) {
    asm volatile("cp.async.cg.shared.global [%0], [%1], 16;\n" :: "r"(saddr), "l"(g) : "memory");
}
__device__ __forceinline__ void cp_commit() { asm volatile("cp.async.commit_group;\n" ::: "memory"); }
__device__ __forceinline__ void cp_wait1()  { asm volatile("cp.async.wait_group 1;\n" ::: "memory"); }
__device__ __forceinline__ void cp_wait0()  { asm volatile("cp.async.wait_group 0;\n" ::: "memory"); }

// ---------------------------------------------------------------------------
// prep: split w_dec (128x256) into bf16 hi/lo
// ---------------------------------------------------------------------------
__global__ void prep_wd(const float* __restrict__ w_dec) {
    int i = blockIdx.x * 256 + threadIdx.x;        // < 32768
    __nv_bfloat16 h, l;
    bf_split(w_dec[i], h, l);
    g_wd_hi[i] = h; g_wd_lo[i] = l;
}

// prep: V_p[r, s*32+l] = vq[(r*16+s), p, l] * (std_p + eps), split hi/lo
__global__ void prep_v(const float* __restrict__ vq, const float* __restrict__ d_std) {
    int i = blockIdx.x * 256 + threadIdx.x;        // < 2097152
    int n = i >> 7, low = i & 127;
    int p = low >> 5, l = low & 31;
    int r = n >> 4, s = n & 15;
    float v = vq[i] * (d_std[p] + 1e-6f);
    __nv_bfloat16 h, lo;
    bf_split(v, h, lo);
    size_t off = (size_t)p * VPITCH + (size_t)r * K2 + s * 32 + l;
    g_v_hi[off] = h; g_v_lo[off] = lo;
}

// aux: xs[t] = sum_i x[t,i];  xb[t,p] = sum_c (sum_s x[t,s*256+c]) * b_dec[p,c]
__global__ void aux_kernel(const float* __restrict__ x, const float* __restrict__ b_dec) {
    __shared__ float sh[256];
    const int t = blockIdx.x, c = threadIdx.x;
    const float* xr = x + (size_t)t * IN_F;
    float xc = 0.f;
#pragma unroll
    for (int s = 0; s < 16; ++s) xc += xr[s * 256 + c];
    sh[c] = xc; __syncthreads();
    for (int o = 128; o > 0; o >>= 1) { if (c < o) sh[c] += sh[c + o]; __syncthreads(); }
    if (c == 0) g_xs[t] = sh[0];
#pragma unroll
    for (int p = 0; p < 4; ++p) {
        __syncthreads();
        sh[c] = xc * b_dec[p * 256 + c]; __syncthreads();
        for (int o = 128; o > 0; o >>= 1) { if (c < o) sh[c] += sh[c + o]; __syncthreads(); }
        if (c == 0) g_xb[t * 4 + p] = sh[0];
    }
}

// ---------------------------------------------------------------------------
// shared-memory tile constants (both GEMMs): 128x32 tiles, padded stride 40
// ---------------------------------------------------------------------------
#define SM_STRIDE 40
#define ARR_ELEMS (128 * SM_STRIDE)
#define STAGE_ELEMS (4 * ARR_ELEMS)
#define STAGE_BYTES (STAGE_ELEMS * 2)
#define OFF_AHI 0
#define OFF_ALO ARR_ELEMS
#define OFF_BHI (2 * ARR_ELEMS)
#define OFF_BLO (3 * ARR_ELEMS)

// ---------------------------------------------------------------------------
// Stage 1: y = x_flat(131072x256) @ wd^T(256x128), bf16x3, y -> hi/lo split
// A converted fp32->bf16 on the fly (LDG + STS); B via cp.async.
// ---------------------------------------------------------------------------
__global__ __launch_bounds__(256)
void y_gemm(const float* __restrict__ x) {
    extern __shared__ __nv_bfloat16 sm[];
    const uint32_t sbase = (uint32_t)__cvta_generic_to_shared(sm);

    const int tid  = threadIdx.x;
    const int lane = tid & 31;
    const int warp = tid >> 5;
    const int wm   = warp >> 2;
    const int wn   = warp & 3;
    const int m0   = blockIdx.x * 128;

    // per-thread load mapping: u -> row u>>2 (0..127), col group (u&3)*8
    const int uA0 = tid, uA1 = tid + 256;
    const int rA0 = uA0 >> 2, cA0 = (uA0 & 3) << 3;
    const int rA1 = uA1 >> 2, cA1 = (uA1 & 3) << 3;

    float acc[4][4][4] = {};
    float4 ra[2][2];

    auto loadA = [&](int kt) {
        // x viewed as (131072 x 256) row-major: row stride = XK = 256 floats
        const float4* p0 = reinterpret_cast<const float4*>(x + (size_t)(m0 + rA0) * XK + kt * 32 + cA0);
        const float4* p1 = reinterpret_cast<const float4*>(x + (size_t)(m0 + rA1) * XK + kt * 32 + cA1);
        ra[0][0] = p0[0]; ra[0][1] = p0[1];
        ra[1][0] = p1[0]; ra[1][1] = p1[1];
    };
    auto stsA = [&](int buf) {
        __nv_bfloat16* base = sm + buf * STAGE_ELEMS;
#pragma unroll
        for (int e = 0; e < 2; ++e) {
            int r = e ? rA1 : rA0, c = e ? cA1 : cA0;
            const float* f = reinterpret_cast<const float*>(ra[e]);
            __nv_bfloat162 hv[4], lv[4];
#pragma unroll
            for (int j = 0; j < 4; ++j) {
                __nv_bfloat16 h0, l0, h1, l1;
                bf_split(f[2 * j], h0, l0);
                bf_split(f[2 * j + 1], h1, l1);
                hv[j] = __halves2bfloat162(h0, h1);
                lv[j] = __halves2bfloat162(l0, l1);
            }
            int o = r * SM_STRIDE + c;
            *reinterpret_cast<uint4*>(base + OFF_AHI + o) = *reinterpret_cast<uint4*>(hv);
            *reinterpret_cast<uint4*>(base + OFF_ALO + o) = *reinterpret_cast<uint4*>(lv);
        }
    };
    auto cpB = [&](int kt) {
        uint32_t st = sbase + (uint32_t)(kt & 1) * STAGE_BYTES;
#pragma unroll
        for (int e = 0; e < 2; ++e) {
            int r = e ? rA1 : rA0, c = e ? cA1 : cA0;
            uint32_t d = (uint32_t)(r * SM_STRIDE + c) * 2;
            const __nv_bfloat16* sh = g_wd_hi + r * 256 + kt * 32 + c;
            const __nv_bfloat16* sl = g_wd_lo + r * 256 + kt * 32 + c;
            cp16(st + OFF_BHI * 2 + d, sh);
            cp16(st + OFF_BLO * 2 + d, sl);
        }
        cp_commit();
    };

    loadA(0); cpB(0); stsA(0);

    for (int kt = 0; kt < 8; ++kt) {
        if (kt < 7) { loadA(kt + 1); cpB(kt + 1); cp_wait1(); }
        else        { cp_wait0(); }
        __syncthreads();

        const uint32_t st = sbase + (uint32_t)(kt & 1) * STAGE_BYTES;
#pragma unroll
        for (int ks = 0; ks < 2; ++ks) {
            uint32_t ahi[4][4], alo[4][4], bhi[4][2], blo[4][2];
            const int arow = wm * 64 + (lane & 15);
            const int acol = ks * 16 + ((lane >> 4) << 3);
#pragma unroll
            for (int mt = 0; mt < 4; ++mt) {
                uint32_t off = (uint32_t)((arow + mt * 16) * SM_STRIDE + acol);
                ldsm_x4(ahi[mt], st + (OFF_AHI + off) * 2);
                ldsm_x4(alo[mt], st + (OFF_ALO + off) * 2);
            }
            const int nrow = wn * 32 + (lane & 7) + ((lane >> 4) << 3);
            const int kcol = ks * 16 + (lane & 8);
#pragma unroll
            for (int ntp = 0; ntp < 2; ++ntp) {
                uint32_t off = (uint32_t)((nrow + ntp * 16) * SM_STRIDE + kcol);
                uint32_t rr[4];
                ldsm_x4(rr, st + (OFF_BHI + off) * 2);
                bhi[2 * ntp][0] = rr[0]; bhi[2 * ntp][1] = rr[1];
                bhi[2 * ntp + 1][0] = rr[2]; bhi[2 * ntp + 1][1] = rr[3];
                ldsm_x4(rr, st + (OFF_BLO + off) * 2);
                blo[2 * ntp][0] = rr[0]; blo[2 * ntp][1] = rr[1];
                blo[2 * ntp + 1][0] = rr[2]; blo[2 * ntp + 1][1] = rr[3];
            }
#pragma unroll
            for (int mt = 0; mt < 4; ++mt)
#pragma unroll
                for (int nt = 0; nt < 4; ++nt) {
                    mma_bf16(acc[mt][nt], ahi[mt], bhi[nt]);
                    mma_bf16(acc[mt][nt], ahi[mt], blo[nt]);
                    mma_bf16(acc[mt][nt], alo[mt], bhi[nt]);
                }
        }
        __syncthreads();
        if (kt < 7) stsA((kt + 1) & 1);
    }

    // epilogue: scatter y (hi/lo) into per-p layout [t, s*32+l]
#pragma unroll
    for (int mt = 0; mt < 4; ++mt) {
#pragma unroll
        for (int nt = 0; nt < 4; ++nt) {
            int j = wn * 32 + nt * 8 + ((lane & 3) << 1);
            int p = j >> 5, l = j & 31;
#pragma unroll
            for (int half = 0; half < 2; ++half) {
                int a  = wm * 64 + mt * 16 + (lane >> 2) + half * 8;
                int mg = m0 + a;
                int t = mg >> 4, s = mg & 15;
                size_t off = (size_t)p * YPITCH + (size_t)t * K2 + s * 32 + l;
                float v0 = acc[mt][nt][2 * half], v1 = acc[mt][nt][2 * half + 1];
                __nv_bfloat16 h0, l0, h1, l1;
                bf_split(v0, h0, l0); bf_split(v1, h1, l1);
                *reinterpret_cast<__nv_bfloat162*>(g_y_hi + off) = __halves2bfloat162(h0, h1);
                *reinterpret_cast<__nv_bfloat162*>(g_y_lo + off) = __halves2bfloat162(l0, l1);
            }
        }
    }
}

// ---------------------------------------------------------------------------
// Stage 2: out[t, p*1024+r] = Y_p(8192x512) @ V_p^T(512x1024) + aux terms
// ---------------------------------------------------------------------------
__device__ __forceinline__ void load_tile2(uint32_t st, int k0,
                                           const __nv_bfloat16* gxh, const __nv_bfloat16* gxl,
                                           const __nv_bfloat16* gwh, const __nv_bfloat16* gwl,
                                           int r0, int c0, int r1, int c1) {
    cp16(st + (uint32_t)(OFF_AHI + r0 * SM_STRIDE + c0) * 2, gxh + (size_t)r0 * K2 + k0 + c0);
    cp16(st + (uint32_t)(OFF_AHI + r1 * SM_STRIDE + c1) * 2, gxh + (size_t)r1 * K2 + k0 + c1);
    cp16(st + (uint32_t)(OFF_ALO + r0 * SM_STRIDE + c0) * 2, gxl + (size_t)r0 * K2 + k0 + c0);
    cp16(st + (uint32_t)(OFF_ALO + r1 * SM_STRIDE + c1) * 2, gxl + (size_t)r1 * K2 + k0 + c1);
    cp16(st + (uint32_t)(OFF_BHI + r0 * SM_STRIDE + c0) * 2, gwh + (size_t)r0 * K2 + k0 + c0);
    cp16(st + (uint32_t)(OFF_BHI + r1 * SM_STRIDE + c1) * 2, gwh + (size_t)r1 * K2 + k0 + c1);
    cp16(st + (uint32_t)(OFF_BLO + r0 * SM_STRIDE + c0) * 2, gwl + (size_t)r0 * K2 + k0 + c0);
    cp16(st + (uint32_t)(OFF_BLO + r1 * SM_STRIDE + c1) * 2, gwl + (size_t)r1 * K2 + k0 + c1);
    cp_commit();
}

__global__ __launch_bounds__(256)
void gemm2(const float* __restrict__ bias, const float* __restrict__ d_mean,
           const float* __restrict__ d_std, float* __restrict__ out) {
    extern __shared__ __nv_bfloat16 sm[];
    const uint32_t sbase = (uint32_t)__cvta_generic_to_shared(sm);

    const int tid  = threadIdx.x;
    const int lane = tid & 31;
    const int warp = tid >> 5;
    const int wm   = warp >> 2;
    const int wn   = warp & 3;
    const int bn   = blockIdx.x;   // 0..7  (128-col tile within p)
    const int bm   = blockIdx.y;   // 0..63 (128-token tile)
    const int p    = blockIdx.z;   // 0..3

    const __nv_bfloat16* gxh = g_y_hi + (size_t)p * YPITCH + (size_t)bm * 128 * K2;
    const __nv_bfloat16* gxl = g_y_lo + (size_t)p * YPITCH + (size_t)bm * 128 * K2;
    const __nv_bfloat16* gwh = g_v_hi + (size_t)p * VPITCH + (size_t)bn * 128 * K2;
    const __nv_bfloat16* gwl = g_v_lo + (size_t)p * VPITCH + (size_t)bn * 128 * K2;

    const int q0 = tid, q1 = tid + 256;
    const int r0 = q0 >> 2, c0 = (q0 & 3) << 3;
    const int r1 = q1 >> 2, c1 = (q1 & 3) << 3;

    float acc[4][4][4] = {};

    load_tile2(sbase, 0, gxh, gxl, gwh, gwl, r0, c0, r1, c1);

    for (int kt = 0; kt < 16; ++kt) {
        if (kt + 1 < 16) {
            load_tile2(sbase + ((kt + 1) & 1) * STAGE_BYTES, (kt + 1) * 32,
                       gxh, gxl, gwh, gwl, r0, c0, r1, c1);
            cp_wait1();
        } else {
            cp_wait0();
        }
        __syncthreads();

        const uint32_t st = sbase + (kt & 1) * STAGE_BYTES;
#pragma unroll
        for (int ks = 0; ks < 2; ++ks) {
            uint32_t ahi[4][4], alo[4][4], bhi[4][2], blo[4][2];
            const int arow = wm * 64 + (lane & 15);
            const int acol = ks * 16 + ((lane >> 4) << 3);
#pragma unroll
            for (int mt = 0; mt < 4; ++mt) {
                uint32_t off = (uint32_t)((arow + mt * 16) * SM_STRIDE + acol);
                ldsm_x4(ahi[mt], st + (OFF_AHI + off) * 2);
                ldsm_x4(alo[mt], st + (OFF_ALO + off) * 2);
            }
            const int nrow = wn * 32 + (lane & 7) + ((lane >> 4) << 3);
            const int kcol = ks * 16 + (lane & 8);
#pragma unroll
            for (int ntp = 0; ntp < 2; ++ntp) {
                uint32_t off = (uint32_t)((nrow + ntp * 16) * SM_STRIDE + kcol);
                uint32_t rr[4];
                ldsm_x4(rr, st + (OFF_BHI + off) * 2);
                bhi[2 * ntp][0] = rr[0]; bhi[2 * ntp][1] = rr[1];
                bhi[2 * ntp + 1][0] = rr[2]; bhi[2 * ntp + 1][1] = rr[3];
                ldsm_x4(rr, st + (OFF_BLO + off) * 2);
                blo[2 * ntp][0] = rr[0]; blo[2 * ntp][1] = rr[1];
                blo[2 * ntp + 1][0] = rr[2]; blo[2 * ntp + 1][1] = rr[3];
            }
#pragma unroll
            for (int mt = 0; mt < 4; ++mt)
#pragma unroll
                for (int nt = 0; nt < 4; ++nt) {
                    mma_bf16(acc[mt][nt], ahi[mt], bhi[nt]);
                    mma_bf16(acc[mt][nt], ahi[mt], blo[nt]);
                    mma_bf16(acc[mt][nt], alo[mt], bhi[nt]);
                }
        }
        __syncthreads();
    }

    const float mean = d_mean[p];
    const float stdp = d_std[p] + 1e-6f;

#pragma unroll
    for (int mt = 0; mt < 4; ++mt) {
        int t0 = bm * 128 + wm * 64 + mt * 16 + (lane >> 2);
        float base0 = mean * g_xs[t0]     + stdp * g_xb[t0 * 4 + p];
        float base1 = mean * g_xs[t0 + 8] + stdp * g_xb[(t0 + 8) * 4 + p];
#pragma unroll
        for (int nt = 0; nt < 4; ++nt) {
            int o = p * 1024 + bn * 128 + wn * 32 + nt * 8 + ((lane & 3) << 1);
            float b0 = bias[o], b1 = bias[o + 1];
            float2* p0 = reinterpret_cast<float2*>(out + (size_t)t0 * OUT_F + o);
            float2* p1 = reinterpret_cast<float2*>(out + (size_t)(t0 + 8) * OUT_F + o);
            *p0 = make_float2(acc[mt][nt][0] + b0 + base0, acc[mt][nt][1] + b1 + base0);
            *p1 = make_float2(acc[mt][nt][2] + b0 + base1, acc[mt][nt][3] + b1 + base1);
        }
    }
}

// ---------------------------------------------------------------------------
extern "C" void kernel_launch(void* const* d_in, const int* in_sizes, int n_in,
                              void* d_out, int out_size) {
    (void)in_sizes; (void)n_in; (void)out_size;
    const float* x      = (const float*)d_in[0];
    const float* vq     = (const float*)d_in[1];
    const float* w_dec  = (const float*)d_in[2];
    const float* b_dec  = (const float*)d_in[3];
    const float* d_mean = (const float*)d_in[4];
    const float* d_std  = (const float*)d_in[5];
    const float* bias   = (const float*)d_in[6];
    float* out = (float*)d_out;

    prep_wd<<<128, 256>>>(w_dec);
    prep_v<<<8192, 256>>>(vq, d_std);
    aux_kernel<<<M_TOK, 256>>>(x, b_dec);

    cudaFuncSetAttribute(y_gemm, cudaFuncAttributeMaxDynamicSharedMemorySize, 2 * STAGE_BYTES);
    y_gemm<<<1024, 256, 2 * STAGE_BYTES>>>(x);

    cudaFuncSetAttribute(gemm2, cudaFuncAttributeMaxDynamicSharedMemorySize, 2 * STAGE_BYTES);
    gemm2<<<dim3(8, 64, 4), 256, 2 * STAGE_BYTES>>>(bias, d_mean, d_std, out);
}

// round 5
// speedup vs baseline: 5.3023x; 1.2420x over previous
#include <cuda_runtime.h>
#include <cuda_bf16.h>
#include <cstdint>

#define IN_F   4096
#define OUT_F  4096
#define M_TOK  8192
#define XK     256                      // stage-1 contraction (x_flat cols)
#define K2     512                      // stage-2 contraction = 16*32
#define YPITCH ((size_t)M_TOK * K2)     // per-p Y matrix elems
#define VPITCH ((size_t)1024 * K2)      // per-p V matrix elems

// Scratch (allocation-free rule: __device__ globals).
__device__ __align__(256) __nv_bfloat16 g_wd_hi[128 * 256];
__device__ __align__(256) __nv_bfloat16 g_wd_lo[128 * 256];
__device__ __align__(256) __nv_bfloat16 g_y_hi[4 * YPITCH];
__device__ __align__(256) __nv_bfloat16 g_y_lo[4 * YPITCH];
__device__ __align__(256) __nv_bfloat16 g_v_hi[4 * VPITCH];
__device__ __align__(256) __nv_bfloat16 g_v_lo[4 * VPITCH];
__device__ float g_xs[M_TOK];
__device__ float g_xb[M_TOK * 4];

// ---------------------------------------------------------------------------
// small helpers
// ---------------------------------------------------------------------------
__device__ __forceinline__ void bf_split(float v, __nv_bfloat16& hi, __nv_bfloat16& lo) {
    hi = __float2bfloat16_rn(v);
    lo = __float2bfloat16_rn(v - __bfloat162float(hi));
}
__device__ __forceinline__ void mma_bf16(float* c, const uint32_t* a, const uint32_t* b) {
    asm volatile(
        "mma.sync.aligned.m16n8k16.row.col.f32.bf16.bf16.f32 "
        "{%0,%1,%2,%3}, {%4,%5,%6,%7}, {%8,%9}, {%0,%1,%2,%3};\n"
        : "+f"(c[0]), "+f"(c[1]), "+f"(c[2]), "+f"(c[3])
        : "r"(a[0]), "r"(a[1]), "r"(a[2]), "r"(a[3]), "r"(b[0]), "r"(b[1]));
}
__device__ __forceinline__ void ldsm_x4(uint32_t* r, uint32_t addr) {
    asm volatile("ldmatrix.sync.aligned.m8n8.x4.shared.b16 {%0,%1,%2,%3}, [%4];\n"
                 : "=r"(r[0]), "=r"(r[1]), "=r"(r[2]), "=r"(r[3]) : "r"(addr));
}
__device__ __forceinline__ void cp16(uint32_t saddr, const void* g) {
    asm volatile("cp.async.cg.shared.global [%0], [%1], 16;\n" :: "r"(saddr), "l"(g) : "memory");
}
__device__ __forceinline__ void cp_commit() { asm volatile("cp.async.commit_group;\n" ::: "memory"); }
__device__ __forceinline__ void cp_wait1()  { asm volatile("cp.async.wait_group 1;\n" ::: "memory"); }
__device__ __forceinline__ void cp_wait0()  { asm volatile("cp.async.wait_group 0;\n" ::: "memory"); }

// ---------------------------------------------------------------------------
// prep: split w_dec (128x256) into bf16 hi/lo
// ---------------------------------------------------------------------------
__global__ void prep_wd(const float* __restrict__ w_dec) {
    int i = blockIdx.x * 256 + threadIdx.x;        // < 32768
    __nv_bfloat16 h, l;
    bf_split(w_dec[i], h, l);
    g_wd_hi[i] = h; g_wd_lo[i] = l;
}

// prep: V_p[r, s*32+l] = vq[(r*16+s), p, l] * (std_p + eps), split hi/lo
__global__ void prep_v(const float* __restrict__ vq, const float* __restrict__ d_std) {
    int i = blockIdx.x * 256 + threadIdx.x;        // < 2097152
    int n = i >> 7, low = i & 127;
    int p = low >> 5, l = low & 31;
    int r = n >> 4, s = n & 15;
    float v = vq[i] * (d_std[p] + 1e-6f);
    __nv_bfloat16 h, lo;
    bf_split(v, h, lo);
    size_t off = (size_t)p * VPITCH + (size_t)r * K2 + s * 32 + l;
    g_v_hi[off] = h; g_v_lo[off] = lo;
}

// aux: xs[t] = sum_i x[t,i];  xb[t,p] = sum_c (sum_s x[t,s*256+c]) * b_dec[p,c]
// shuffle-based 5-value reduction
__global__ void aux_kernel(const float* __restrict__ x, const float* __restrict__ b_dec) {
    __shared__ float sh[8][5];
    const int t = blockIdx.x, c = threadIdx.x;
    const int lane = c & 31, w = c >> 5;
    const float* xr = x + (size_t)t * IN_F;
    float xc = 0.f;
#pragma unroll
    for (int s = 0; s < 16; ++s) xc += xr[s * 256 + c];
    float v[5];
    v[0] = xc;
    v[1] = xc * b_dec[c];
    v[2] = xc * b_dec[256 + c];
    v[3] = xc * b_dec[512 + c];
    v[4] = xc * b_dec[768 + c];
#pragma unroll
    for (int o = 16; o > 0; o >>= 1)
#pragma unroll
        for (int j = 0; j < 5; ++j)
            v[j] += __shfl_xor_sync(0xffffffffu, v[j], o);
    if (lane == 0)
#pragma unroll
        for (int j = 0; j < 5; ++j) sh[w][j] = v[j];
    __syncthreads();
    if (w == 0 && lane < 8) {
        float a0 = sh[lane][0], a1 = sh[lane][1], a2 = sh[lane][2],
              a3 = sh[lane][3], a4 = sh[lane][4];
#pragma unroll
        for (int o = 4; o > 0; o >>= 1) {
            a0 += __shfl_xor_sync(0xffu, a0, o);
            a1 += __shfl_xor_sync(0xffu, a1, o);
            a2 += __shfl_xor_sync(0xffu, a2, o);
            a3 += __shfl_xor_sync(0xffu, a3, o);
            a4 += __shfl_xor_sync(0xffu, a4, o);
        }
        if (lane == 0) {
            g_xs[t] = a0;
            g_xb[t * 4 + 0] = a1; g_xb[t * 4 + 1] = a2;
            g_xb[t * 4 + 2] = a3; g_xb[t * 4 + 3] = a4;
        }
    }
}

// ---------------------------------------------------------------------------
// shared-memory tile constants (both GEMMs): 128x32 tiles, padded stride 40
// ---------------------------------------------------------------------------
#define SM_STRIDE 40
#define ARR_ELEMS (128 * SM_STRIDE)
#define STAGE_ELEMS (4 * ARR_ELEMS)
#define STAGE_BYTES (STAGE_ELEMS * 2)
#define OFF_AHI 0
#define OFF_ALO ARR_ELEMS
#define OFF_BHI (2 * ARR_ELEMS)
#define OFF_BLO (3 * ARR_ELEMS)

// shared inner compute for one 32-wide K slab (2 ks-steps), A per-mt transient
__device__ __forceinline__ void tile_mmas(uint32_t st, int wm, int wn, int lane,
                                          float acc[4][4][4]) {
#pragma unroll
    for (int ks = 0; ks < 2; ++ks) {
        uint32_t bhi[4][2], blo[4][2];
        const int nrow = wn * 32 + (lane & 7) + ((lane >> 4) << 3);
        const int kcol = ks * 16 + (lane & 8);
#pragma unroll
        for (int ntp = 0; ntp < 2; ++ntp) {
            uint32_t off = (uint32_t)((nrow + ntp * 16) * SM_STRIDE + kcol);
            uint32_t rr[4];
            ldsm_x4(rr, st + (OFF_BHI + off) * 2);
            bhi[2 * ntp][0] = rr[0]; bhi[2 * ntp][1] = rr[1];
            bhi[2 * ntp + 1][0] = rr[2]; bhi[2 * ntp + 1][1] = rr[3];
            ldsm_x4(rr, st + (OFF_BLO + off) * 2);
            blo[2 * ntp][0] = rr[0]; blo[2 * ntp][1] = rr[1];
            blo[2 * ntp + 1][0] = rr[2]; blo[2 * ntp + 1][1] = rr[3];
        }
        const int arow = wm * 64 + (lane & 15);
        const int acol = ks * 16 + ((lane >> 4) << 3);
#pragma unroll
        for (int mt = 0; mt < 4; ++mt) {
            uint32_t ahi[4], alo[4];
            uint32_t off = (uint32_t)((arow + mt * 16) * SM_STRIDE + acol);
            ldsm_x4(ahi, st + (OFF_AHI + off) * 2);
            ldsm_x4(alo, st + (OFF_ALO + off) * 2);
#pragma unroll
            for (int nt = 0; nt < 4; ++nt) mma_bf16(acc[mt][nt], ahi, bhi[nt]);
#pragma unroll
            for (int nt = 0; nt < 4; ++nt) mma_bf16(acc[mt][nt], ahi, blo[nt]);
#pragma unroll
            for (int nt = 0; nt < 4; ++nt) mma_bf16(acc[mt][nt], alo, bhi[nt]);
        }
    }
}

// ---------------------------------------------------------------------------
// Stage 1: y = x_flat(131072x256) @ wd^T(256x128), bf16x3, y -> hi/lo split
// ---------------------------------------------------------------------------
__global__ __launch_bounds__(256, 2)
void y_gemm(const float* __restrict__ x) {
    extern __shared__ __nv_bfloat16 sm[];
    const uint32_t sbase = (uint32_t)__cvta_generic_to_shared(sm);

    const int tid  = threadIdx.x;
    const int lane = tid & 31;
    const int warp = tid >> 5;
    const int wm   = warp >> 2;
    const int wn   = warp & 3;
    const int m0   = blockIdx.x * 128;

    const int uA0 = tid, uA1 = tid + 256;
    const int rA0 = uA0 >> 2, cA0 = (uA0 & 3) << 3;
    const int rA1 = uA1 >> 2, cA1 = (uA1 & 3) << 3;

    float acc[4][4][4] = {};
    float4 ra[2][2];

    auto loadA = [&](int kt) {
        const float4* p0 = reinterpret_cast<const float4*>(x + (size_t)(m0 + rA0) * XK + kt * 32 + cA0);
        const float4* p1 = reinterpret_cast<const float4*>(x + (size_t)(m0 + rA1) * XK + kt * 32 + cA1);
        ra[0][0] = p0[0]; ra[0][1] = p0[1];
        ra[1][0] = p1[0]; ra[1][1] = p1[1];
    };
    auto stsA = [&](int buf) {
        __nv_bfloat16* base = sm + buf * STAGE_ELEMS;
#pragma unroll
        for (int e = 0; e < 2; ++e) {
            int r = e ? rA1 : rA0, c = e ? cA1 : cA0;
            const float* f = reinterpret_cast<const float*>(ra[e]);
            __nv_bfloat162 hv[4], lv[4];
#pragma unroll
            for (int j = 0; j < 4; ++j) {
                __nv_bfloat16 h0, l0, h1, l1;
                bf_split(f[2 * j], h0, l0);
                bf_split(f[2 * j + 1], h1, l1);
                hv[j] = __halves2bfloat162(h0, h1);
                lv[j] = __halves2bfloat162(l0, l1);
            }
            int o = r * SM_STRIDE + c;
            *reinterpret_cast<uint4*>(base + OFF_AHI + o) = *reinterpret_cast<uint4*>(hv);
            *reinterpret_cast<uint4*>(base + OFF_ALO + o) = *reinterpret_cast<uint4*>(lv);
        }
    };
    auto cpB = [&](int kt) {
        uint32_t st = sbase + (uint32_t)(kt & 1) * STAGE_BYTES;
#pragma unroll
        for (int e = 0; e < 2; ++e) {
            int r = e ? rA1 : rA0, c = e ? cA1 : cA0;
            uint32_t d = (uint32_t)(r * SM_STRIDE + c) * 2;
            cp16(st + OFF_BHI * 2 + d, g_wd_hi + r * 256 + kt * 32 + c);
            cp16(st + OFF_BLO * 2 + d, g_wd_lo + r * 256 + kt * 32 + c);
        }
        cp_commit();
    };

    loadA(0); cpB(0); stsA(0);

    for (int kt = 0; kt < 8; ++kt) {
        if (kt < 7) { loadA(kt + 1); cpB(kt + 1); cp_wait1(); }
        else        { cp_wait0(); }
        __syncthreads();

        tile_mmas(sbase + (uint32_t)(kt & 1) * STAGE_BYTES, wm, wn, lane, acc);

        __syncthreads();
        if (kt < 7) stsA((kt + 1) & 1);
    }

    // epilogue: scatter y (hi/lo) into per-p layout [t, s*32+l]
#pragma unroll
    for (int mt = 0; mt < 4; ++mt) {
#pragma unroll
        for (int nt = 0; nt < 4; ++nt) {
            int j = wn * 32 + nt * 8 + ((lane & 3) << 1);
            int p = j >> 5, l = j & 31;
#pragma unroll
            for (int half = 0; half < 2; ++half) {
                int a  = wm * 64 + mt * 16 + (lane >> 2) + half * 8;
                int mg = m0 + a;
                int t = mg >> 4, s = mg & 15;
                size_t off = (size_t)p * YPITCH + (size_t)t * K2 + s * 32 + l;
                float v0 = acc[mt][nt][2 * half], v1 = acc[mt][nt][2 * half + 1];
                __nv_bfloat16 h0, l0, h1, l1;
                bf_split(v0, h0, l0); bf_split(v1, h1, l1);
                *reinterpret_cast<__nv_bfloat162*>(g_y_hi + off) = __halves2bfloat162(h0, h1);
                *reinterpret_cast<__nv_bfloat162*>(g_y_lo + off) = __halves2bfloat162(l0, l1);
            }
        }
    }
}

// ---------------------------------------------------------------------------
// Stage 2: out[t, p*1024+r] = Y_p(8192x512) @ V_p^T(512x1024) + aux terms
// ---------------------------------------------------------------------------
__device__ __forceinline__ void load_tile2(uint32_t st, int k0,
                                           const __nv_bfloat16* gxh, const __nv_bfloat16* gxl,
                                           const __nv_bfloat16* gwh, const __nv_bfloat16* gwl,
                                           int r0, int c0, int r1, int c1) {
    cp16(st + (uint32_t)(OFF_AHI + r0 * SM_STRIDE + c0) * 2, gxh + (size_t)r0 * K2 + k0 + c0);
    cp16(st + (uint32_t)(OFF_AHI + r1 * SM_STRIDE + c1) * 2, gxh + (size_t)r1 * K2 + k0 + c1);
    cp16(st + (uint32_t)(OFF_ALO + r0 * SM_STRIDE + c0) * 2, gxl + (size_t)r0 * K2 + k0 + c0);
    cp16(st + (uint32_t)(OFF_ALO + r1 * SM_STRIDE + c1) * 2, gxl + (size_t)r1 * K2 + k0 + c1);
    cp16(st + (uint32_t)(OFF_BHI + r0 * SM_STRIDE + c0) * 2, gwh + (size_t)r0 * K2 + k0 + c0);
    cp16(st + (uint32_t)(OFF_BHI + r1 * SM_STRIDE + c1) * 2, gwh + (size_t)r1 * K2 + k0 + c1);
    cp16(st + (uint32_t)(OFF_BLO + r0 * SM_STRIDE + c0) * 2, gwl + (size_t)r0 * K2 + k0 + c0);
    cp16(st + (uint32_t)(OFF_BLO + r1 * SM_STRIDE + c1) * 2, gwl + (size_t)r1 * K2 + k0 + c1);
    cp_commit();
}

__global__ __launch_bounds__(256, 2)
void gemm2(const float* __restrict__ bias, const float* __restrict__ d_mean,
           const float* __restrict__ d_std, float* __restrict__ out) {
    extern __shared__ __nv_bfloat16 sm[];
    const uint32_t sbase = (uint32_t)__cvta_generic_to_shared(sm);

    const int tid  = threadIdx.x;
    const int lane = tid & 31;
    const int warp = tid >> 5;
    const int wm   = warp >> 2;
    const int wn   = warp & 3;
    const int bn   = blockIdx.x;   // 0..7  (128-col tile within p)
    const int bm   = blockIdx.y;   // 0..63 (128-token tile)
    const int p    = blockIdx.z;   // 0..3

    const __nv_bfloat16* gxh = g_y_hi + (size_t)p * YPITCH + (size_t)bm * 128 * K2;
    const __nv_bfloat16* gxl = g_y_lo + (size_t)p * YPITCH + (size_t)bm * 128 * K2;
    const __nv_bfloat16* gwh = g_v_hi + (size_t)p * VPITCH + (size_t)bn * 128 * K2;
    const __nv_bfloat16* gwl = g_v_lo + (size_t)p * VPITCH + (size_t)bn * 128 * K2;

    const int q0 = tid, q1 = tid + 256;
    const int r0 = q0 >> 2, c0 = (q0 & 3) << 3;
    const int r1 = q1 >> 2, c1 = (q1 & 3) << 3;

    float acc[4][4][4] = {};

    load_tile2(sbase, 0, gxh, gxl, gwh, gwl, r0, c0, r1, c1);

    for (int kt = 0; kt < 16; ++kt) {
        if (kt + 1 < 16) {
            load_tile2(sbase + ((kt + 1) & 1) * STAGE_BYTES, (kt + 1) * 32,
                       gxh, gxl, gwh, gwl, r0, c0, r1, c1);
            cp_wait1();
        } else {
            cp_wait0();
        }
        __syncthreads();

        tile_mmas(sbase + (uint32_t)(kt & 1) * STAGE_BYTES, wm, wn, lane, acc);

        __syncthreads();
    }

    const float mean = d_mean[p];
    const float stdp = d_std[p] + 1e-6f;

#pragma unroll
    for (int mt = 0; mt < 4; ++mt) {
        int t0 = bm * 128 + wm * 64 + mt * 16 + (lane >> 2);
        float base0 = mean * g_xs[t0]     + stdp * g_xb[t0 * 4 + p];
        float base1 = mean * g_xs[t0 + 8] + stdp * g_xb[(t0 + 8) * 4 + p];
#pragma unroll
        for (int nt = 0; nt < 4; ++nt) {
            int o = p * 1024 + bn * 128 + wn * 32 + nt * 8 + ((lane & 3) << 1);
            float b0 = bias[o], b1 = bias[o + 1];
            float2* p0 = reinterpret_cast<float2*>(out + (size_t)t0 * OUT_F + o);
            float2* p1 = reinterpret_cast<float2*>(out + (size_t)(t0 + 8) * OUT_F + o);
            *p0 = make_float2(acc[mt][nt][0] + b0 + base0, acc[mt][nt][1] + b1 + base0);
            *p1 = make_float2(acc[mt][nt][2] + b0 + base1, acc[mt][nt][3] + b1 + base1);
        }
    }
}

// ---------------------------------------------------------------------------
extern "C" void kernel_launch(void* const* d_in, const int* in_sizes, int n_in,
                              void* d_out, int out_size) {
    (void)in_sizes; (void)n_in; (void)out_size;
    const float* x      = (const float*)d_in[0];
    const float* vq     = (const float*)d_in[1];
    const float* w_dec  = (const float*)d_in[2];
    const float* b_dec  = (const float*)d_in[3];
    const float* d_mean = (const float*)d_in[4];
    const float* d_std  = (const float*)d_in[5];
    const float* bias   = (const float*)d_in[6];
    float* out = (float*)d_out;

    prep_wd<<<128, 256>>>(w_dec);
    prep_v<<<8192, 256>>>(vq, d_std);
    aux_kernel<<<M_TOK, 256>>>(x, b_dec);

    cudaFuncSetAttribute(y_gemm, cudaFuncAttributeMaxDynamicSharedMemorySize, 2 * STAGE_BYTES);
    y_gemm<<<1024, 256, 2 * STAGE_BYTES>>>(x);

    cudaFuncSetAttribute(gemm2, cudaFuncAttributeMaxDynamicSharedMemorySize, 2 * STAGE_BYTES);
    gemm2<<<dim3(8, 64, 4), 256, 2 * STAGE_BYTES>>>(bias, d_mean, d_std, out);
}

// round 6
// speedup vs baseline: 5.7702x; 1.0882x over previous
#include <cuda_runtime.h>
#include <cuda_bf16.h>
#include <cstdint>

#define IN_F   4096
#define OUT_F  4096
#define M_TOK  8192
#define XK     256                      // stage-1 contraction (x_flat cols)
#define K2     512                      // stage-2 contraction = 16*32
#define YPITCH ((size_t)M_TOK * K2)     // per-p Y matrix elems
#define VPITCH ((size_t)1024 * K2)      // per-p V matrix elems

// Scratch (allocation-free rule: __device__ globals).
__device__ __align__(256) __nv_bfloat16 g_wd_hi[128 * 256];
__device__ __align__(256) __nv_bfloat16 g_wd_lo[128 * 256];
__device__ __align__(256) __nv_bfloat16 g_y_hi[4 * YPITCH];
__device__ __align__(256) __nv_bfloat16 g_y_lo[4 * YPITCH];
__device__ __align__(256) __nv_bfloat16 g_v_hi[4 * VPITCH];
__device__ __align__(256) __nv_bfloat16 g_v_lo[4 * VPITCH];
__device__ float g_xs[M_TOK];
__device__ float g_xb[M_TOK * 4];

// ---------------------------------------------------------------------------
// small helpers
// ---------------------------------------------------------------------------
__device__ __forceinline__ void bf_split(float v, __nv_bfloat16& hi, __nv_bfloat16& lo) {
    hi = __float2bfloat16_rn(v);
    lo = __float2bfloat16_rn(v - __bfloat162float(hi));
}
__device__ __forceinline__ void mma_bf16(float* c, const uint32_t* a, const uint32_t* b) {
    asm volatile(
        "mma.sync.aligned.m16n8k16.row.col.f32.bf16.bf16.f32 "
        "{%0,%1,%2,%3}, {%4,%5,%6,%7}, {%8,%9}, {%0,%1,%2,%3};\n"
        : "+f"(c[0]), "+f"(c[1]), "+f"(c[2]), "+f"(c[3])
        : "r"(a[0]), "r"(a[1]), "r"(a[2]), "r"(a[3]), "r"(b[0]), "r"(b[1]));
}
__device__ __forceinline__ void ldsm_x4(uint32_t* r, uint32_t addr) {
    asm volatile("ldmatrix.sync.aligned.m8n8.x4.shared.b16 {%0,%1,%2,%3}, [%4];\n"
                 : "=r"(r[0]), "=r"(r[1]), "=r"(r[2]), "=r"(r[3]) : "r"(addr));
}
__device__ __forceinline__ void cp16(uint32_t saddr, const void* g) {
    asm volatile("cp.async.cg.shared.global [%0], [%1], 16;\n" :: "r"(saddr), "l"(g) : "memory");
}
__device__ __forceinline__ void cp_commit() { asm volatile("cp.async.commit_group;\n" ::: "memory"); }
__device__ __forceinline__ void cp_wait1()  { asm volatile("cp.async.wait_group 1;\n" ::: "memory"); }
__device__ __forceinline__ void cp_wait0()  { asm volatile("cp.async.wait_group 0;\n" ::: "memory"); }

// Packed swizzle: 2 m-rows (32 bf16 each) per 128B line. r:0..127, c:0..31.
__device__ __forceinline__ uint32_t swz(int r, int c) {
    int line = r >> 1;
    int q = ((r & 1) << 2) | (c >> 3);
    return (uint32_t)((line << 7) | ((q ^ (line & 7)) << 4) | ((c & 7) << 1));
}

// ---------------------------------------------------------------------------
// prep kernels (unchanged semantics)
// ---------------------------------------------------------------------------
__global__ void prep_wd(const float* __restrict__ w_dec) {
    int i = blockIdx.x * 256 + threadIdx.x;
    __nv_bfloat16 h, l;
    bf_split(w_dec[i], h, l);
    g_wd_hi[i] = h; g_wd_lo[i] = l;
}

__global__ void prep_v(const float* __restrict__ vq, const float* __restrict__ d_std) {
    int i = blockIdx.x * 256 + threadIdx.x;
    int n = i >> 7, low = i & 127;
    int p = low >> 5, l = low & 31;
    int r = n >> 4, s = n & 15;
    float v = vq[i] * (d_std[p] + 1e-6f);
    __nv_bfloat16 h, lo;
    bf_split(v, h, lo);
    size_t off = (size_t)p * VPITCH + (size_t)r * K2 + s * 32 + l;
    g_v_hi[off] = h; g_v_lo[off] = lo;
}

__global__ void aux_kernel(const float* __restrict__ x, const float* __restrict__ b_dec) {
    __shared__ float sh[8][5];
    const int t = blockIdx.x, c = threadIdx.x;
    const int lane = c & 31, w = c >> 5;
    const float* xr = x + (size_t)t * IN_F;
    float xc = 0.f;
#pragma unroll
    for (int s = 0; s < 16; ++s) xc += xr[s * 256 + c];
    float v[5];
    v[0] = xc;
    v[1] = xc * b_dec[c];
    v[2] = xc * b_dec[256 + c];
    v[3] = xc * b_dec[512 + c];
    v[4] = xc * b_dec[768 + c];
#pragma unroll
    for (int o = 16; o > 0; o >>= 1)
#pragma unroll
        for (int j = 0; j < 5; ++j)
            v[j] += __shfl_xor_sync(0xffffffffu, v[j], o);
    if (lane == 0)
#pragma unroll
        for (int j = 0; j < 5; ++j) sh[w][j] = v[j];
    __syncthreads();
    if (w == 0 && lane < 8) {
        float a0 = sh[lane][0], a1 = sh[lane][1], a2 = sh[lane][2],
              a3 = sh[lane][3], a4 = sh[lane][4];
#pragma unroll
        for (int o = 4; o > 0; o >>= 1) {
            a0 += __shfl_xor_sync(0xffu, a0, o);
            a1 += __shfl_xor_sync(0xffu, a1, o);
            a2 += __shfl_xor_sync(0xffu, a2, o);
            a3 += __shfl_xor_sync(0xffu, a3, o);
            a4 += __shfl_xor_sync(0xffu, a4, o);
        }
        if (lane == 0) {
            g_xs[t] = a0;
            g_xb[t * 4 + 0] = a1; g_xb[t * 4 + 1] = a2;
            g_xb[t * 4 + 2] = a3; g_xb[t * 4 + 3] = a4;
        }
    }
}

// ---------------------------------------------------------------------------
// smem tile constants: swizzled 128x32 arrays of 8KB, stage = 32KB, 3 stages
// ---------------------------------------------------------------------------
#define ARR_BYTES 8192
#define OFF_AHI 0
#define OFF_ALO 8192
#define OFF_BHI 16384
#define OFF_BLO 24576
#define STAGE_BYTES 32768
#define DYN_SMEM (3 * STAGE_BYTES + 128)

// inner compute for one 32-wide K slab (2 ks-steps), A per-mt transient
__device__ __forceinline__ void tile_mmas(uint32_t st, int wm, int wn, int lane,
                                          float acc[4][4][4]) {
#pragma unroll
    for (int ks = 0; ks < 2; ++ks) {
        uint32_t bhi[4][2], blo[4][2];
        const int brow = wn * 32 + (lane & 7) + ((lane >> 4) << 3);
        const int bcol = ks * 16 + (lane & 8);
#pragma unroll
        for (int ntp = 0; ntp < 2; ++ntp) {
            uint32_t rr[4];
            ldsm_x4(rr, st + OFF_BHI + swz(brow + ntp * 16, bcol));
            bhi[2 * ntp][0] = rr[0]; bhi[2 * ntp][1] = rr[1];
            bhi[2 * ntp + 1][0] = rr[2]; bhi[2 * ntp + 1][1] = rr[3];
            ldsm_x4(rr, st + OFF_BLO + swz(brow + ntp * 16, bcol));
            blo[2 * ntp][0] = rr[0]; blo[2 * ntp][1] = rr[1];
            blo[2 * ntp + 1][0] = rr[2]; blo[2 * ntp + 1][1] = rr[3];
        }
        const int arow = wm * 64 + (lane & 15);
        const int acol = ks * 16 + ((lane >> 4) << 3);
#pragma unroll
        for (int mt = 0; mt < 4; ++mt) {
            uint32_t ahi[4], alo[4];
            ldsm_x4(ahi, st + OFF_AHI + swz(arow + mt * 16, acol));
            ldsm_x4(alo, st + OFF_ALO + swz(arow + mt * 16, acol));
#pragma unroll
            for (int nt = 0; nt < 4; ++nt) mma_bf16(acc[mt][nt], ahi, bhi[nt]);
#pragma unroll
            for (int nt = 0; nt < 4; ++nt) mma_bf16(acc[mt][nt], ahi, blo[nt]);
#pragma unroll
            for (int nt = 0; nt < 4; ++nt) mma_bf16(acc[mt][nt], alo, bhi[nt]);
        }
    }
}

// ---------------------------------------------------------------------------
// Stage 1: y = x_flat(131072x256) @ wd^T(256x128), bf16x3, 3-stage pipeline
// ---------------------------------------------------------------------------
__global__ __launch_bounds__(256, 2)
void y_gemm(const float* __restrict__ x) {
    extern __shared__ __nv_bfloat16 smraw[];
    const uint32_t sdata = ((uint32_t)__cvta_generic_to_shared(smraw) + 127u) & ~127u;

    const int tid  = threadIdx.x;
    const int lane = tid & 31;
    const int warp = tid >> 5;
    const int wm   = warp >> 2;
    const int wn   = warp & 3;
    const int m0   = blockIdx.x * 128;

    const int uA0 = tid, uA1 = tid + 256;
    const int rA0 = uA0 >> 2, cA0 = (uA0 & 3) << 3;
    const int rA1 = uA1 >> 2, cA1 = (uA1 & 3) << 3;
    const uint32_t dA0 = swz(rA0, cA0), dA1 = swz(rA1, cA1);

    float acc[4][4][4] = {};
    float4 ra[2][2];

    auto loadA = [&](int kt) {
        const float4* p0 = reinterpret_cast<const float4*>(x + (size_t)(m0 + rA0) * XK + kt * 32 + cA0);
        const float4* p1 = reinterpret_cast<const float4*>(x + (size_t)(m0 + rA1) * XK + kt * 32 + cA1);
        ra[0][0] = p0[0]; ra[0][1] = p0[1];
        ra[1][0] = p1[0]; ra[1][1] = p1[1];
    };
    auto stsA = [&](uint32_t st) {
#pragma unroll
        for (int e = 0; e < 2; ++e) {
            const float* f = reinterpret_cast<const float*>(ra[e]);
            __nv_bfloat162 hv[4], lv[4];
#pragma unroll
            for (int j = 0; j < 4; ++j) {
                __nv_bfloat16 h0, l0, h1, l1;
                bf_split(f[2 * j], h0, l0);
                bf_split(f[2 * j + 1], h1, l1);
                hv[j] = __halves2bfloat162(h0, h1);
                lv[j] = __halves2bfloat162(l0, l1);
            }
            uint32_t d = e ? dA1 : dA0;
            asm volatile("st.shared.v4.b32 [%0], {%1,%2,%3,%4};\n" ::
                "r"(st + OFF_AHI + d),
                "r"(*reinterpret_cast<uint32_t*>(&hv[0])), "r"(*reinterpret_cast<uint32_t*>(&hv[1])),
                "r"(*reinterpret_cast<uint32_t*>(&hv[2])), "r"(*reinterpret_cast<uint32_t*>(&hv[3])));
            asm volatile("st.shared.v4.b32 [%0], {%1,%2,%3,%4};\n" ::
                "r"(st + OFF_ALO + d),
                "r"(*reinterpret_cast<uint32_t*>(&lv[0])), "r"(*reinterpret_cast<uint32_t*>(&lv[1])),
                "r"(*reinterpret_cast<uint32_t*>(&lv[2])), "r"(*reinterpret_cast<uint32_t*>(&lv[3])));
        }
    };
    auto cpB = [&](uint32_t st, int kt) {
        cp16(st + OFF_BHI + dA0, g_wd_hi + rA0 * 256 + kt * 32 + cA0);
        cp16(st + OFF_BLO + dA0, g_wd_lo + rA0 * 256 + kt * 32 + cA0);
        cp16(st + OFF_BHI + dA1, g_wd_hi + rA1 * 256 + kt * 32 + cA1);
        cp16(st + OFF_BLO + dA1, g_wd_lo + rA1 * 256 + kt * 32 + cA1);
        cp_commit();
    };
    auto stg = [&](int s) -> uint32_t { return sdata + (uint32_t)s * STAGE_BYTES; };

    // prologue: stage 0 and 1 fully produced; A(2) in registers
    loadA(0); stsA(stg(0)); cpB(stg(0), 0);
    loadA(1); stsA(stg(1)); cpB(stg(1), 1);
    loadA(2);

    int cur = 0;
    for (int kt = 0; kt < 8; ++kt) {
        if (kt < 7) cp_wait1(); else cp_wait0();
        __syncthreads();
        if (kt + 2 < 8) {
            int nx = cur + 2; if (nx >= 3) nx -= 3;
            stsA(stg(nx));
            cpB(stg(nx), kt + 2);
            if (kt + 3 < 8) loadA(kt + 3);
        }
        tile_mmas(stg(cur), wm, wn, lane, acc);
        if (++cur == 3) cur = 0;
    }

    // epilogue: scatter y (hi/lo) into per-p layout [t, s*32+l]
#pragma unroll
    for (int mt = 0; mt < 4; ++mt) {
#pragma unroll
        for (int nt = 0; nt < 4; ++nt) {
            int j = wn * 32 + nt * 8 + ((lane & 3) << 1);
            int p = j >> 5, l = j & 31;
#pragma unroll
            for (int half = 0; half < 2; ++half) {
                int a  = wm * 64 + mt * 16 + (lane >> 2) + half * 8;
                int mg = m0 + a;
                int t = mg >> 4, s = mg & 15;
                size_t off = (size_t)p * YPITCH + (size_t)t * K2 + s * 32 + l;
                float v0 = acc[mt][nt][2 * half], v1 = acc[mt][nt][2 * half + 1];
                __nv_bfloat16 h0, l0, h1, l1;
                bf_split(v0, h0, l0); bf_split(v1, h1, l1);
                *reinterpret_cast<__nv_bfloat162*>(g_y_hi + off) = __halves2bfloat162(h0, h1);
                *reinterpret_cast<__nv_bfloat162*>(g_y_lo + off) = __halves2bfloat162(l0, l1);
            }
        }
    }
}

// ---------------------------------------------------------------------------
// Stage 2: out[t, p*1024+r] = Y_p(8192x512) @ V_p^T(512x1024) + aux terms
// ---------------------------------------------------------------------------
__global__ __launch_bounds__(256, 2)
void gemm2(const float* __restrict__ bias, const float* __restrict__ d_mean,
           const float* __restrict__ d_std, float* __restrict__ out) {
    extern __shared__ __nv_bfloat16 smraw[];
    const uint32_t sdata = ((uint32_t)__cvta_generic_to_shared(smraw) + 127u) & ~127u;

    const int tid  = threadIdx.x;
    const int lane = tid & 31;
    const int warp = tid >> 5;
    const int wm   = warp >> 2;
    const int wn   = warp & 3;
    const int bn   = blockIdx.x;   // 0..7  (128-col tile within p)
    const int bm   = blockIdx.y;   // 0..63 (128-token tile)
    const int p    = blockIdx.z;   // 0..3

    const __nv_bfloat16* gxh = g_y_hi + (size_t)p * YPITCH + (size_t)bm * 128 * K2;
    const __nv_bfloat16* gxl = g_y_lo + (size_t)p * YPITCH + (size_t)bm * 128 * K2;
    const __nv_bfloat16* gwh = g_v_hi + (size_t)p * VPITCH + (size_t)bn * 128 * K2;
    const __nv_bfloat16* gwl = g_v_lo + (size_t)p * VPITCH + (size_t)bn * 128 * K2;

    const int u0 = tid, u1 = tid + 256;
    const int r0 = u0 >> 2, c0 = (u0 & 3) << 3;
    const int r1 = u1 >> 2, c1 = (u1 & 3) << 3;
    const uint32_t d0 = swz(r0, c0), d1 = swz(r1, c1);

    auto load_tile = [&](uint32_t st, int k0) {
        cp16(st + OFF_AHI + d0, gxh + (size_t)r0 * K2 + k0 + c0);
        cp16(st + OFF_AHI + d1, gxh + (size_t)r1 * K2 + k0 + c1);
        cp16(st + OFF_ALO + d0, gxl + (size_t)r0 * K2 + k0 + c0);
        cp16(st + OFF_ALO + d1, gxl + (size_t)r1 * K2 + k0 + c1);
        cp16(st + OFF_BHI + d0, gwh + (size_t)r0 * K2 + k0 + c0);
        cp16(st + OFF_BHI + d1, gwh + (size_t)r1 * K2 + k0 + c1);
        cp16(st + OFF_BLO + d0, gwl + (size_t)r0 * K2 + k0 + c0);
        cp16(st + OFF_BLO + d1, gwl + (size_t)r1 * K2 + k0 + c1);
        cp_commit();
    };
    auto stg = [&](int s) -> uint32_t { return sdata + (uint32_t)s * STAGE_BYTES; };

    float acc[4][4][4] = {};

    load_tile(stg(0), 0);
    load_tile(stg(1), 32);

    int cur = 0;
    for (int kt = 0; kt < 16; ++kt) {
        if (kt < 15) cp_wait1(); else cp_wait0();
        __syncthreads();
        if (kt + 2 < 16) {
            int nx = cur + 2; if (nx >= 3) nx -= 3;
            load_tile(stg(nx), (kt + 2) * 32);
        }
        tile_mmas(stg(cur), wm, wn, lane, acc);
        if (++cur == 3) cur = 0;
    }

    const float mean = d_mean[p];
    const float stdp = d_std[p] + 1e-6f;

#pragma unroll
    for (int mt = 0; mt < 4; ++mt) {
        int t0 = bm * 128 + wm * 64 + mt * 16 + (lane >> 2);
        float base0 = mean * g_xs[t0]     + stdp * g_xb[t0 * 4 + p];
        float base1 = mean * g_xs[t0 + 8] + stdp * g_xb[(t0 + 8) * 4 + p];
#pragma unroll
        for (int nt = 0; nt < 4; ++nt) {
            int o = p * 1024 + bn * 128 + wn * 32 + nt * 8 + ((lane & 3) << 1);
            float b0 = bias[o], b1 = bias[o + 1];
            float2* p0 = reinterpret_cast<float2*>(out + (size_t)t0 * OUT_F + o);
            float2* p1 = reinterpret_cast<float2*>(out + (size_t)(t0 + 8) * OUT_F + o);
            *p0 = make_float2(acc[mt][nt][0] + b0 + base0, acc[mt][nt][1] + b1 + base0);
            *p1 = make_float2(acc[mt][nt][2] + b0 + base1, acc[mt][nt][3] + b1 + base1);
        }
    }
}

// ---------------------------------------------------------------------------
extern "C" void kernel_launch(void* const* d_in, const int* in_sizes, int n_in,
                              void* d_out, int out_size) {
    (void)in_sizes; (void)n_in; (void)out_size;
    const float* x      = (const float*)d_in[0];
    const float* vq     = (const float*)d_in[1];
    const float* w_dec  = (const float*)d_in[2];
    const float* b_dec  = (const float*)d_in[3];
    const float* d_mean = (const float*)d_in[4];
    const float* d_std  = (const float*)d_in[5];
    const float* bias   = (const float*)d_in[6];
    float* out = (float*)d_out;

    prep_wd<<<128, 256>>>(w_dec);
    prep_v<<<8192, 256>>>(vq, d_std);
    aux_kernel<<<M_TOK, 256>>>(x, b_dec);

    cudaFuncSetAttribute(y_gemm, cudaFuncAttributeMaxDynamicSharedMemorySize, DYN_SMEM);
    y_gemm<<<1024, 256, DYN_SMEM>>>(x);

    cudaFuncSetAttribute(gemm2, cudaFuncAttributeMaxDynamicSharedMemorySize, DYN_SMEM);
    gemm2<<<dim3(8, 64, 4), 256, DYN_SMEM>>>(bias, d_mean, d_std, out);
}

// round 7
// speedup vs baseline: 11.5374x; 1.9995x over previous
#include <cuda_runtime.h>
#include <cuda_bf16.h>
#include <cuda_fp16.h>
#include <cstdint>

#define IN_F   4096
#define OUT_F  4096
#define M_TOK  8192
#define XK     256                      // stage-1 contraction (x_flat cols)
#define K2     512                      // stage-2 contraction = 16*32
#define YPITCH ((size_t)M_TOK * K2)     // per-p Y matrix elems
#define VPITCH ((size_t)1024 * K2)      // per-p V matrix elems

// Scratch (allocation-free rule: __device__ globals).
__device__ __align__(256) __half g_wd[128 * 256];
__device__ __align__(256) __half g_y[4 * YPITCH];
__device__ __align__(256) __half g_v[4 * VPITCH];
__device__ float g_xs[M_TOK];
__device__ float g_xb[M_TOK * 4];

// ---------------------------------------------------------------------------
// helpers
// ---------------------------------------------------------------------------
__device__ __forceinline__ void mma_f16(float* c, const uint32_t* a, const uint32_t* b) {
    asm volatile(
        "mma.sync.aligned.m16n8k16.row.col.f32.f16.f16.f32 "
        "{%0,%1,%2,%3}, {%4,%5,%6,%7}, {%8,%9}, {%0,%1,%2,%3};\n"
        : "+f"(c[0]), "+f"(c[1]), "+f"(c[2]), "+f"(c[3])
        : "r"(a[0]), "r"(a[1]), "r"(a[2]), "r"(a[3]), "r"(b[0]), "r"(b[1]));
}
__device__ __forceinline__ void ldsm_x4(uint32_t* r, uint32_t addr) {
    asm volatile("ldmatrix.sync.aligned.m8n8.x4.shared.b16 {%0,%1,%2,%3}, [%4];\n"
                 : "=r"(r[0]), "=r"(r[1]), "=r"(r[2]), "=r"(r[3]) : "r"(addr));
}
__device__ __forceinline__ void cp16(uint32_t saddr, const void* g) {
    asm volatile("cp.async.cg.shared.global [%0], [%1], 16;\n" :: "r"(saddr), "l"(g) : "memory");
}
__device__ __forceinline__ void cp_commit() { asm volatile("cp.async.commit_group;\n" ::: "memory"); }
__device__ __forceinline__ void cp_wait1()  { asm volatile("cp.async.wait_group 1;\n" ::: "memory"); }
__device__ __forceinline__ void cp_wait0()  { asm volatile("cp.async.wait_group 0;\n" ::: "memory"); }

// swizzle for 32-col tiles: 2 rows per 128B line. r:0..127, c:0..31 (fp16)
__device__ __forceinline__ uint32_t swz32(int r, int c) {
    int line = r >> 1;
    int q = ((r & 1) << 2) | (c >> 3);
    return (uint32_t)((line << 7) | ((q ^ (line & 7)) << 4) | ((c & 7) << 1));
}
// swizzle for 64-col tiles: 1 row per 128B line. r:0..127, c:0..63 (fp16)
__device__ __forceinline__ uint32_t swz64(int r, int c) {
    int q = c >> 3;
    return (uint32_t)((r << 7) | (((q ^ (r & 7)) & 7) << 4) | ((c & 7) << 1));
}

// ---------------------------------------------------------------------------
// prep kernels
// ---------------------------------------------------------------------------
__global__ void prep_wd(const float* __restrict__ w_dec) {
    int i = blockIdx.x * 256 + threadIdx.x;        // < 32768
    g_wd[i] = __float2half_rn(w_dec[i]);
}

__global__ void prep_v(const float* __restrict__ vq, const float* __restrict__ d_std) {
    int i = blockIdx.x * 256 + threadIdx.x;        // < 2097152
    int n = i >> 7, low = i & 127;
    int p = low >> 5, l = low & 31;
    int r = n >> 4, s = n & 15;
    float v = vq[i] * (d_std[p] + 1e-6f);
    g_v[(size_t)p * VPITCH + (size_t)r * K2 + s * 32 + l] = __float2half_rn(v);
}

__global__ void aux_kernel(const float* __restrict__ x, const float* __restrict__ b_dec) {
    __shared__ float sh[8][5];
    const int t = blockIdx.x, c = threadIdx.x;
    const int lane = c & 31, w = c >> 5;
    const float* xr = x + (size_t)t * IN_F;
    float xc = 0.f;
#pragma unroll
    for (int s = 0; s < 16; ++s) xc += xr[s * 256 + c];
    float v[5];
    v[0] = xc;
    v[1] = xc * b_dec[c];
    v[2] = xc * b_dec[256 + c];
    v[3] = xc * b_dec[512 + c];
    v[4] = xc * b_dec[768 + c];
#pragma unroll
    for (int o = 16; o > 0; o >>= 1)
#pragma unroll
        for (int j = 0; j < 5; ++j)
            v[j] += __shfl_xor_sync(0xffffffffu, v[j], o);
    if (lane == 0)
#pragma unroll
        for (int j = 0; j < 5; ++j) sh[w][j] = v[j];
    __syncthreads();
    if (w == 0 && lane < 8) {
        float a0 = sh[lane][0], a1 = sh[lane][1], a2 = sh[lane][2],
              a3 = sh[lane][3], a4 = sh[lane][4];
#pragma unroll
        for (int o = 4; o > 0; o >>= 1) {
            a0 += __shfl_xor_sync(0xffu, a0, o);
            a1 += __shfl_xor_sync(0xffu, a1, o);
            a2 += __shfl_xor_sync(0xffu, a2, o);
            a3 += __shfl_xor_sync(0xffu, a3, o);
            a4 += __shfl_xor_sync(0xffu, a4, o);
        }
        if (lane == 0) {
            g_xs[t] = a0;
            g_xb[t * 4 + 0] = a1; g_xb[t * 4 + 1] = a2;
            g_xb[t * 4 + 2] = a3; g_xb[t * 4 + 3] = a4;
        }
    }
}

// ---------------------------------------------------------------------------
// Stage 1: y = x_flat(131072x256) @ wd^T(256x128), fp16 mma
// K-slab 32, 3-stage pipeline (stage = A 8KB + B 8KB = 16KB)
// ---------------------------------------------------------------------------
#define S1_OFF_B 8192
#define S1_STAGE 16384
#define S1_DYN   (3 * S1_STAGE + 128)

__global__ __launch_bounds__(256, 2)
void y_gemm(const float* __restrict__ x) {
    extern __shared__ __half smraw[];
    const uint32_t sdata = ((uint32_t)__cvta_generic_to_shared(smraw) + 127u) & ~127u;

    const int tid  = threadIdx.x;
    const int lane = tid & 31;
    const int warp = tid >> 5;
    const int wm   = warp >> 2;
    const int wn   = warp & 3;
    const int m0   = blockIdx.x * 128;

    // A/B chunk mapping: 512 chunks of 8 elems (16B fp16 / 32B fp32), 2/thread
    const int u0 = tid, u1 = tid + 256;
    const int r0 = u0 >> 2, c0 = (u0 & 3) << 3;
    const int r1 = u1 >> 2, c1 = (u1 & 3) << 3;
    const uint32_t d0 = swz32(r0, c0), d1 = swz32(r1, c1);

    float acc[4][4][4] = {};
    float4 ra[2][2];

    auto loadA = [&](int kt) {
        const float4* p0 = reinterpret_cast<const float4*>(x + (size_t)(m0 + r0) * XK + kt * 32 + c0);
        const float4* p1 = reinterpret_cast<const float4*>(x + (size_t)(m0 + r1) * XK + kt * 32 + c1);
        ra[0][0] = p0[0]; ra[0][1] = p0[1];
        ra[1][0] = p1[0]; ra[1][1] = p1[1];
    };
    auto stsA = [&](uint32_t st) {
#pragma unroll
        for (int e = 0; e < 2; ++e) {
            const float* f = reinterpret_cast<const float*>(ra[e]);
            __half2 hv[4];
#pragma unroll
            for (int j = 0; j < 4; ++j)
                hv[j] = __halves2half2(__float2half_rn(f[2 * j]), __float2half_rn(f[2 * j + 1]));
            asm volatile("st.shared.v4.b32 [%0], {%1,%2,%3,%4};\n" ::
                "r"(st + (e ? d1 : d0)),
                "r"(*reinterpret_cast<uint32_t*>(&hv[0])), "r"(*reinterpret_cast<uint32_t*>(&hv[1])),
                "r"(*reinterpret_cast<uint32_t*>(&hv[2])), "r"(*reinterpret_cast<uint32_t*>(&hv[3])));
        }
    };
    auto cpB = [&](uint32_t st, int kt) {
        cp16(st + S1_OFF_B + d0, g_wd + r0 * 256 + kt * 32 + c0);
        cp16(st + S1_OFF_B + d1, g_wd + r1 * 256 + kt * 32 + c1);
        cp_commit();
    };
    auto stg = [&](int s) -> uint32_t { return sdata + (uint32_t)s * S1_STAGE; };

    // prologue
    loadA(0); stsA(stg(0)); cpB(stg(0), 0);
    loadA(1); stsA(stg(1)); cpB(stg(1), 1);
    loadA(2);

    int cur = 0;
    for (int kt = 0; kt < 8; ++kt) {
        if (kt < 7) cp_wait1(); else cp_wait0();
        __syncthreads();
        int nx = cur + 2; if (nx >= 3) nx -= 3;
        if (kt + 2 < 8) cpB(stg(nx), kt + 2);   // cheap prefetch before MMAs

        // MMAs for stage cur (K-slab 32)
#pragma unroll
        for (int ks = 0; ks < 2; ++ks) {
            uint32_t bf[4][2];
            const int brow = wn * 32 + (lane & 7) + ((lane >> 4) << 3);
            const int bcol = ks * 16 + (lane & 8);
#pragma unroll
            for (int ntp = 0; ntp < 2; ++ntp) {
                uint32_t rr[4];
                ldsm_x4(rr, stg(cur) + S1_OFF_B + swz32(brow + ntp * 16, bcol));
                bf[2 * ntp][0] = rr[0]; bf[2 * ntp][1] = rr[1];
                bf[2 * ntp + 1][0] = rr[2]; bf[2 * ntp + 1][1] = rr[3];
            }
            const int arow = wm * 64 + (lane & 15);
            const int acol = ks * 16 + ((lane >> 4) << 3);
#pragma unroll
            for (int mt = 0; mt < 4; ++mt) {
                uint32_t af[4];
                ldsm_x4(af, stg(cur) + swz32(arow + mt * 16, acol));
#pragma unroll
                for (int nt = 0; nt < 4; ++nt) mma_f16(acc[mt][nt], af, bf[nt]);
            }
        }

        if (kt + 2 < 8) {
            stsA(stg(nx));                       // register-heavy work after MMAs
            if (kt + 3 < 8) loadA(kt + 3);
        }
        if (++cur == 3) cur = 0;
    }

    // epilogue: scatter y into per-p layout [t, s*32+l], fp16
#pragma unroll
    for (int mt = 0; mt < 4; ++mt) {
#pragma unroll
        for (int nt = 0; nt < 4; ++nt) {
            int j = wn * 32 + nt * 8 + ((lane & 3) << 1);
            int p = j >> 5, l = j & 31;
#pragma unroll
            for (int half = 0; half < 2; ++half) {
                int a  = wm * 64 + mt * 16 + (lane >> 2) + half * 8;
                int mg = m0 + a;
                int t = mg >> 4, s = mg & 15;
                size_t off = (size_t)p * YPITCH + (size_t)t * K2 + s * 32 + l;
                *reinterpret_cast<__half2*>(g_y + off) =
                    __halves2half2(__float2half_rn(acc[mt][nt][2 * half]),
                                   __float2half_rn(acc[mt][nt][2 * half + 1]));
            }
        }
    }
}

// ---------------------------------------------------------------------------
// Stage 2: out[t, p*1024+r] = Y_p(8192x512) @ V_p^T(512x1024) + aux
// K-slab 64, 3-stage pipeline (stage = A 16KB + B 16KB = 32KB)
// ---------------------------------------------------------------------------
#define S2_OFF_B 16384
#define S2_STAGE 32768
#define S2_DYN   (3 * S2_STAGE + 128)

__global__ __launch_bounds__(256, 2)
void gemm2(const float* __restrict__ bias, const float* __restrict__ d_mean,
           const float* __restrict__ d_std, float* __restrict__ out) {
    extern __shared__ __half smraw[];
    const uint32_t sdata = ((uint32_t)__cvta_generic_to_shared(smraw) + 127u) & ~127u;

    const int tid  = threadIdx.x;
    const int lane = tid & 31;
    const int warp = tid >> 5;
    const int wm   = warp >> 2;
    const int wn   = warp & 3;
    const int bn   = blockIdx.x;   // 0..7
    const int bm   = blockIdx.y;   // 0..63
    const int p    = blockIdx.z;   // 0..3

    const __half* gx = g_y + (size_t)p * YPITCH + (size_t)bm * 128 * K2;
    const __half* gw = g_v + (size_t)p * VPITCH + (size_t)bn * 128 * K2;

    // 1024 chunks of 16B per 128x64 tile -> 4/thread
    int rr_[4], cc_[4];
    uint32_t dd_[4];
#pragma unroll
    for (int e = 0; e < 4; ++e) {
        int u = tid + e * 256;
        rr_[e] = u >> 3; cc_[e] = (u & 7) << 3;
        dd_[e] = swz64(rr_[e], cc_[e]);
    }

    auto load_tile = [&](uint32_t st, int k0) {
#pragma unroll
        for (int e = 0; e < 4; ++e)
            cp16(st + dd_[e], gx + (size_t)rr_[e] * K2 + k0 + cc_[e]);
#pragma unroll
        for (int e = 0; e < 4; ++e)
            cp16(st + S2_OFF_B + dd_[e], gw + (size_t)rr_[e] * K2 + k0 + cc_[e]);
        cp_commit();
    };
    auto stg = [&](int s) -> uint32_t { return sdata + (uint32_t)s * S2_STAGE; };

    float acc[4][4][4] = {};

    load_tile(stg(0), 0);
    load_tile(stg(1), 64);

    int cur = 0;
    for (int kt = 0; kt < 8; ++kt) {
        if (kt < 7) cp_wait1(); else cp_wait0();
        __syncthreads();
        if (kt + 2 < 8) {
            int nx = cur + 2; if (nx >= 3) nx -= 3;
            load_tile(stg(nx), (kt + 2) * 64);
        }

        const uint32_t st = stg(cur);
#pragma unroll
        for (int ks = 0; ks < 4; ++ks) {
            uint32_t bf[4][2];
            const int brow = wn * 32 + (lane & 7) + ((lane >> 4) << 3);
            const int bcol = ks * 16 + (lane & 8);
#pragma unroll
            for (int ntp = 0; ntp < 2; ++ntp) {
                uint32_t rr[4];
                ldsm_x4(rr, st + S2_OFF_B + swz64(brow + ntp * 16, bcol));
                bf[2 * ntp][0] = rr[0]; bf[2 * ntp][1] = rr[1];
                bf[2 * ntp + 1][0] = rr[2]; bf[2 * ntp + 1][1] = rr[3];
            }
            const int arow = wm * 64 + (lane & 15);
            const int acol = ks * 16 + ((lane >> 4) << 3);
#pragma unroll
            for (int mt = 0; mt < 4; ++mt) {
                uint32_t af[4];
                ldsm_x4(af, st + swz64(arow + mt * 16, acol));
#pragma unroll
                for (int nt = 0; nt < 4; ++nt) mma_f16(acc[mt][nt], af, bf[nt]);
            }
        }
        if (++cur == 3) cur = 0;
    }

    const float mean = d_mean[p];
    const float stdp = d_std[p] + 1e-6f;

#pragma unroll
    for (int mt = 0; mt < 4; ++mt) {
        int t0 = bm * 128 + wm * 64 + mt * 16 + (lane >> 2);
        float base0 = mean * g_xs[t0]     + stdp * g_xb[t0 * 4 + p];
        float base1 = mean * g_xs[t0 + 8] + stdp * g_xb[(t0 + 8) * 4 + p];
#pragma unroll
        for (int nt = 0; nt < 4; ++nt) {
            int o = p * 1024 + bn * 128 + wn * 32 + nt * 8 + ((lane & 3) << 1);
            float b0 = bias[o], b1 = bias[o + 1];
            float2* p0 = reinterpret_cast<float2*>(out + (size_t)t0 * OUT_F + o);
            float2* p1 = reinterpret_cast<float2*>(out + (size_t)(t0 + 8) * OUT_F + o);
            *p0 = make_float2(acc[mt][nt][0] + b0 + base0, acc[mt][nt][1] + b1 + base0);
            *p1 = make_float2(acc[mt][nt][2] + b0 + base1, acc[mt][nt][3] + b1 + base1);
        }
    }
}

// ---------------------------------------------------------------------------
extern "C" void kernel_launch(void* const* d_in, const int* in_sizes, int n_in,
                              void* d_out, int out_size) {
    (void)in_sizes; (void)n_in; (void)out_size;
    const float* x      = (const float*)d_in[0];
    const float* vq     = (const float*)d_in[1];
    const float* w_dec  = (const float*)d_in[2];
    const float* b_dec  = (const float*)d_in[3];
    const float* d_mean = (const float*)d_in[4];
    const float* d_std  = (const float*)d_in[5];
    const float* bias   = (const float*)d_in[6];
    float* out = (float*)d_out;

    prep_wd<<<128, 256>>>(w_dec);
    prep_v<<<8192, 256>>>(vq, d_std);
    aux_kernel<<<M_TOK, 256>>>(x, b_dec);

    cudaFuncSetAttribute(y_gemm, cudaFuncAttributeMaxDynamicSharedMemorySize, S1_DYN);
    y_gemm<<<1024, 256, S1_DYN>>>(x);

    cudaFuncSetAttribute(gemm2, cudaFuncAttributeMaxDynamicSharedMemorySize, S2_DYN);
    gemm2<<<dim3(8, 64, 4), 256, S2_DYN>>>(bias, d_mean, d_std, out);
}